// round 13
// baseline (speedup 1.0000x reference)
#include <cuda_runtime.h>
#include <cstdint>

#define T_STEPS 4096
#define IN_SZ   1024
#define H       2048
#define MOD     256
#define NMOD    8
#define NCTA    128    // persistent CTAs for recurrence (< 148 SMs -> co-resident)
#define NREP    8      // replicas of the published-h table (reader CTA c uses c&7)

// ---------------------------------------------------------------------------
// Scratch (static device memory; no allocations allowed)
// ---------------------------------------------------------------------------
__device__ float g_U[(size_t)T_STEPS * H];   // 32MB: U[t-1][r] = x·W_ih^T + b_ih + b_hh

// Tagged published h: word = (step_tag << 32) | f32_bits.
//   g_tv[(((rep*2 + slot)*NMOD + module) << 8) + col], col = 0..255 within module.
//   slot = (epoch >> module) & 1 (double buffer per module epoch). 256KB total.
#define GTV_WORDS (NREP * 2 * NMOD * 256)    // 32768 u64
__device__ __align__(16) unsigned long long g_tv[GTV_WORDS];

// ---------------------------------------------------------------------------
// memory-model primitives (relaxed 64-bit: single-word atomicity carries tag+val)
// ---------------------------------------------------------------------------
__device__ __forceinline__ unsigned long long ld_rlx(const unsigned long long* p) {
    unsigned long long v;
    asm volatile("ld.relaxed.gpu.global.b64 %0, [%1];" : "=l"(v) : "l"(p));
    return v;
}
__device__ __forceinline__ void st_rlx(unsigned long long* p, unsigned long long v) {
    asm volatile("st.relaxed.gpu.global.b64 [%0], %1;" :: "l"(p), "l"(v));
}
__device__ __forceinline__ float lof(unsigned long long v) {
    return __uint_as_float((unsigned)v);
}

// ---------------------------------------------------------------------------
// Kernel 1: zero g_tv (tags must be 0 each launch: epoch 0 == h=0) + input
// projection for active (step, module) pairs. grid = (512, 8).
// Blocks with blk = j*512+bx < 64 zero g_tv (64*256 float4 = 256KB exactly).
// CTA (bx, j) with bx < nb computes 8 active steps of module j.
// ---------------------------------------------------------------------------
__global__ __launch_bounds__(256) void input_gemm_kernel(
    const float* __restrict__ x, const float* __restrict__ W_ih,
    const float* __restrict__ b_ih, const float* __restrict__ b_hh)
{
    const int j   = blockIdx.y;
    const int bx  = blockIdx.x;
    const int tid = threadIdx.x;

    {   // zero the tagged table (bounded: 32768 u64 = 16384 float4)
        const int blk = j * 512 + bx;
        if (blk < 64)
            ((float4*)g_tv)[blk * 256 + tid] = make_float4(0.f, 0.f, 0.f, 0.f);
    }

    const int nb = (T_STEPS >> j) >> 3;
    if (bx >= nb) return;
    const int p = 1 << j;

    __shared__ float4 xs[8][IN_SZ / 4];                     // 32 KB
    #pragma unroll
    for (int k = 0; k < 8; k++) {
        int t = p * (bx * 8 + k + 1);                       // 1-indexed active step
        const float4* xr = (const float4*)(x + (size_t)(t - 1) * IN_SZ);
        xs[k][tid] = xr[tid];
    }
    __syncthreads();

    const int r = j * MOD + tid;
    const float4* wr = (const float4*)(W_ih + (size_t)r * IN_SZ);
    float acc[8] = {0.f, 0.f, 0.f, 0.f, 0.f, 0.f, 0.f, 0.f};
    #pragma unroll 2
    for (int q = 0; q < IN_SZ / 4; q++) {
        const float4 w = wr[q];
        #pragma unroll
        for (int k = 0; k < 8; k++) {
            const float4 xv = xs[k][q];
            acc[k] = fmaf(w.x, xv.x, fmaf(w.y, xv.y, fmaf(w.z, xv.z, fmaf(w.w, xv.w, acc[k]))));
        }
    }
    const float b = b_ih[r] + b_hh[r];
    #pragma unroll
    for (int k = 0; k < 8; k++) {
        int t = p * (bx * 8 + k + 1);
        g_U[(size_t)(t - 1) * H + r] = acc[k] + b;
    }
}

// ---------------------------------------------------------------------------
// Kernel 2: barrier-free persistent recurrence. 128 CTAs x 256 threads.
// Warp w of CTA c owns rows r0 = w*256 + 2c, r1 = r0+1 and iterates ONLY its
// active steps t = period, 2*period, ... (period = 2^w). h lives in registers
// (hq[16] float4/lane); refreshed modules are loaded as tagged u64 directly
// from g_tv replica (c&7). No __syncthreads, no smem. Order per step:
//   U load -> refresh modules 7..1 -> partial dot (q=2..15, overlaps module-0
//   publish latency) -> spin module 0 -> dot q=0..1 -> butterfly -> tanh ->
//   publish (16 lanes, one tagged store each, 8 replicas) -> output burst.
// ---------------------------------------------------------------------------
__global__ __launch_bounds__(256, 1) void recurrence_kernel(
    const float* __restrict__ W_hh, float* __restrict__ out)
{
    const int tid = threadIdx.x;
    const int w   = tid >> 5;
    const int l   = tid & 31;
    const int c   = blockIdx.x;                 // 0..127
    const int rep = c & (NREP - 1);
    const int r0  = w * MOD + 2 * c;
    const int r1  = r0 + 1;
    const int period = 1 << w;

    // This warp's two W_hh rows -> registers (128 f32/lane), hq mapping:
    // lane l covers columns 128q + 4l + {0..3}; module(q) = q>>1.
    float4 w0[16], w1[16];
    #pragma unroll
    for (int q = 0; q < 16; q++) {
        w0[q] = *(const float4*)(W_hh + (size_t)r0 * H + q * 128 + l * 4);
        w1[q] = *(const float4*)(W_hh + (size_t)r1 * H + q * 128 + l * 4);
    }

    // Register h cache, init epoch 0 (h = 0).
    float4 hq[16];
    #pragma unroll
    for (int q = 0; q < 16; q++) hq[q] = make_float4(0.f, 0.f, 0.f, 0.f);

    // Zero-fill output rows for steps 1 .. period-1 (module inactive, h=0).
    if (l == 0)
        for (int k = 1; k < period; k++)
            *(float2*)(out + (size_t)(k - 1) * H + r0) = make_float2(0.f, 0.f);

    int budget = 1 << 22;                       // warp-uniform hang guard

    for (int t = period; t <= T_STEPS; t += period) {
        const unsigned tm = (unsigned)(t - 1);
        unsigned prev = (unsigned)(t - period);
        prev = prev ? prev - 1u : 0u;           // epochs loaded as of last active step

        // U for this step (DRAM; issued first, consumed last -> hidden).
        const float2 uu = *(const float2*)(g_U + (size_t)tm * H + r0);

        // ---- refresh modules 7..1 whose epoch advanced (usually satisfied
        //      on first poll: they published >= 1 step ago) ----
        #pragma unroll
        for (int i = NMOD - 1; i >= 1; i--) {
            const unsigned e  = tm >> i;        // current epoch index of module i
            if (e != (prev >> i)) {
                const unsigned s0 = e << i;     // expected tag
                const int slot = (int)(e & 1u);
                const unsigned long long* base =
                    g_tv + (((size_t)(rep * 2 + slot) * NMOD + i) << 8);
                unsigned long long v[8];
                bool ok;
                do {
                    ok = true;
                    #pragma unroll
                    for (int d = 0; d < 4; d++) {
                        v[d]     = ld_rlx(base + 4 * l + d);
                        v[4 + d] = ld_rlx(base + 128 + 4 * l + d);
                    }
                    #pragma unroll
                    for (int d = 0; d < 8; d++) ok &= ((unsigned)(v[d] >> 32) == s0);
                    if (--budget < 0) ok = true;            // uniform bail-out
                } while (__any_sync(0xffffffffu, !ok));
                hq[2 * i]     = make_float4(lof(v[0]), lof(v[1]), lof(v[2]), lof(v[3]));
                hq[2 * i + 1] = make_float4(lof(v[4]), lof(v[5]), lof(v[6]), lof(v[7]));
            }
        }

        // ---- partial dot over modules 1..7 (overlaps module-0 publish) ----
        float a0x = 0.f, a0y = 0.f, a0z = 0.f, a0w = 0.f;
        float a1x = 0.f, a1y = 0.f, a1z = 0.f, a1w = 0.f;
        #pragma unroll
        for (int q = 2; q < 16; q++) {
            const float4 hv = hq[q];
            a0x = fmaf(hv.x, w0[q].x, a0x);  a0y = fmaf(hv.y, w0[q].y, a0y);
            a0z = fmaf(hv.z, w0[q].z, a0z);  a0w = fmaf(hv.w, w0[q].w, a0w);
            a1x = fmaf(hv.x, w1[q].x, a1x);  a1y = fmaf(hv.y, w1[q].y, a1y);
            a1z = fmaf(hv.z, w1[q].z, a1z);  a1w = fmaf(hv.w, w1[q].w, a1w);
        }

        // ---- module 0 last (the freshest: published at step t-1) ----
        if (tm != prev) {                       // false only at w=0, t=1
            const unsigned s0 = tm;
            const int slot = (int)(tm & 1u);
            const unsigned long long* base =
                g_tv + (((size_t)(rep * 2 + slot) * NMOD + 0) << 8);
            unsigned long long v[8];
            bool ok;
            do {
                ok = true;
                #pragma unroll
                for (int d = 0; d < 4; d++) {
                    v[d]     = ld_rlx(base + 4 * l + d);
                    v[4 + d] = ld_rlx(base + 128 + 4 * l + d);
                }
                #pragma unroll
                for (int d = 0; d < 8; d++) ok &= ((unsigned)(v[d] >> 32) == s0);
                if (--budget < 0) ok = true;
            } while (__any_sync(0xffffffffu, !ok));
            hq[0] = make_float4(lof(v[0]), lof(v[1]), lof(v[2]), lof(v[3]));
            hq[1] = make_float4(lof(v[4]), lof(v[5]), lof(v[6]), lof(v[7]));
        }
        #pragma unroll
        for (int q = 0; q < 2; q++) {
            const float4 hv = hq[q];
            a0x = fmaf(hv.x, w0[q].x, a0x);  a0y = fmaf(hv.y, w0[q].y, a0y);
            a0z = fmaf(hv.z, w0[q].z, a0z);  a0w = fmaf(hv.w, w0[q].w, a0w);
            a1x = fmaf(hv.x, w1[q].x, a1x);  a1y = fmaf(hv.y, w1[q].y, a1y);
            a1z = fmaf(hv.z, w1[q].z, a1z);  a1w = fmaf(hv.w, w1[q].w, a1w);
        }

        float a0 = (a0x + a0y) + (a0z + a0w);
        float a1 = (a1x + a1y) + (a1z + a1w);
        #pragma unroll
        for (int off = 16; off >= 1; off >>= 1) {
            a0 += __shfl_xor_sync(0xffffffffu, a0, off);
            a1 += __shfl_xor_sync(0xffffffffu, a1, off);
        }
        const float hc0 = tanhf(uu.x + a0);
        const float hc1 = tanhf(uu.y + a1);

        // ---- publish: 16 lanes, one tagged store each (col {2c,2c+1} x 8 reps) ----
        if (l < 16) {
            const int rp    = l & 7;
            const int which = l >> 3;
            const int col   = 2 * c + which;
            const int slot  = (int)(((unsigned)t >> w) & 1u);
            const unsigned long long word =
                ((unsigned long long)(unsigned)t << 32) |
                (unsigned long long)__float_as_uint(which ? hc1 : hc0);
            st_rlx(g_tv + (((size_t)(rp * 2 + slot) * NMOD + w) << 8) + col, word);
        }

        // ---- output burst: this value holds for steps t .. t+period-1 ----
        if (l == 0) {
            const int kmax = min(period, T_STEPS - t + 1);
            for (int k = 0; k < kmax; k++)
                *(float2*)(out + (size_t)(tm + k) * H + r0) = make_float2(hc0, hc1);
        }
    }
}

// ---------------------------------------------------------------------------
extern "C" void kernel_launch(void* const* d_in, const int* in_sizes, int n_in,
                              void* d_out, int out_size)
{
    const float* x    = (const float*)d_in[0];
    const float* W_ih = (const float*)d_in[1];
    const float* W_hh = (const float*)d_in[2];
    const float* b_ih = (const float*)d_in[3];
    const float* b_hh = (const float*)d_in[4];
    float* out = (float*)d_out;

    input_gemm_kernel<<<dim3(512, NMOD), 256>>>(x, W_ih, b_ih, b_hh);
    recurrence_kernel<<<NCTA, 256>>>(W_hh, out);
}

// round 14
// speedup vs baseline: 2.8576x; 2.8576x over previous
#include <cuda_runtime.h>
#include <cstdint>

#define T_STEPS 4096
#define IN_SZ   1024
#define H       2048
#define MOD     256
#define NMOD    8
#define NWORK   128    // worker CTAs (16 per module); grid padded to 148
#define NGRID   148

// ---------------------------------------------------------------------------
// Scratch (static device memory; no allocations allowed)
// ---------------------------------------------------------------------------
__device__ float g_U[(size_t)T_STEPS * H];   // 32MB: U[t-1][r] = x·W_ih^T + b_ih + b_hh
__device__ unsigned g_cnt[NMOD * 32];        // per-module arrival counter, 128B stride

// ---------------------------------------------------------------------------
// memory-model primitives
// ---------------------------------------------------------------------------
__device__ __forceinline__ unsigned ld_acq_u32(const unsigned* p) {
    unsigned v;
    asm volatile("ld.acquire.gpu.global.u32 %0, [%1];" : "=r"(v) : "l"(p));
    return v;
}
__device__ __forceinline__ void st_rlx_u64(unsigned long long* p, unsigned long long v) {
    asm volatile("st.relaxed.gpu.global.b64 [%0], %1;" :: "l"(p), "l"(v));
}
__device__ __forceinline__ void red_rel_add(unsigned* p, unsigned v) {
    asm volatile("red.release.gpu.global.add.u32 [%0], %1;" :: "l"(p), "r"(v));
}

// ---------------------------------------------------------------------------
// Kernel 1: zero counters + input projection for active (step, module) pairs.
// grid = (512, 8); CTA (bx, j) handles 8 consecutive active steps of module j.
// (Stream order guarantees counters are zero before the recurrence launch.)
// ---------------------------------------------------------------------------
__global__ __launch_bounds__(256) void input_gemm_kernel(
    const float* __restrict__ x, const float* __restrict__ W_ih,
    const float* __restrict__ b_ih, const float* __restrict__ b_hh)
{
    const int j   = blockIdx.y;
    const int bx  = blockIdx.x;
    const int tid = threadIdx.x;

    if (j == 0 && bx == 0 && tid < NMOD * 32) g_cnt[tid] = 0u;

    const int nb = (T_STEPS >> j) >> 3;
    if (bx >= nb) return;
    const int p = 1 << j;

    __shared__ float4 xs[8][IN_SZ / 4];                     // 32 KB
    #pragma unroll
    for (int k = 0; k < 8; k++) {
        int t = p * (bx * 8 + k + 1);                       // 1-indexed active step
        const float4* xr = (const float4*)(x + (size_t)(t - 1) * IN_SZ);
        xs[k][tid] = xr[tid];
    }
    __syncthreads();

    const int r = j * MOD + tid;
    const float4* wr = (const float4*)(W_ih + (size_t)r * IN_SZ);
    float acc[8] = {0.f, 0.f, 0.f, 0.f, 0.f, 0.f, 0.f, 0.f};
    #pragma unroll 2
    for (int q = 0; q < IN_SZ / 4; q++) {
        const float4 w = wr[q];
        #pragma unroll
        for (int k = 0; k < 8; k++) {
            const float4 xv = xs[k][q];
            acc[k] = fmaf(w.x, xv.x, fmaf(w.y, xv.y, fmaf(w.z, xv.z, fmaf(w.w, xv.w, acc[k]))));
        }
    }
    const float b = b_ih[r] + b_hh[r];
    #pragma unroll
    for (int k = 0; k < 8; k++) {
        int t = p * (bx * 8 + k + 1);
        g_U[(size_t)(t - 1) * H + r] = acc[k] + b;
    }
}

// ---------------------------------------------------------------------------
// Kernel 2: module-partitioned persistent recurrence.
// Worker CTA g (< 128): module j = g>>4, sub s = g&15; warp w owns rows
// r0 = j*256 + s*16 + 2w, r1 = r0+1. Iterates ONLY t = 2^j, 2*2^j, ...
// h cached in registers (hq[16] float4/lane); refresh module i when its
// epoch (t-1)>>i advanced since the previous activation, by polling the
// module counter (ld.acquire, expect 16*epoch) then reading the h block
// from OUT itself: epoch e of module i lives at out[(e<<i - 1)*H + i*256].
// Publish = lane0 st.relaxed of the first burst row -> __syncthreads
// (CTA-scope release/acquire, transitive) -> tid0 red.release(counter+1),
// then all lanes write the remaining carried-output rows of the burst.
// No inter-warp coupling beyond one intra-CTA bar; sync population per
// module = 16 CTAs.
// ---------------------------------------------------------------------------
__global__ __launch_bounds__(256, 1) void recurrence_kernel(
    const float* __restrict__ W_hh, float* __restrict__ out)
{
    const int g = blockIdx.x;
    if (g >= NWORK) return;                     // grid padded to 148
    const int j = g >> 4;                       // owned module
    const int s = g & 15;                       // sub-index within module
    const int tid = threadIdx.x;
    const int w   = tid >> 5;
    const int l   = tid & 31;
    const int r0  = j * MOD + s * 16 + 2 * w;
    const int r1  = r0 + 1;
    const int period = 1 << j;

    // This warp's two W_hh rows -> registers (128 f32/lane):
    // lane l covers columns 128q + 4l + {0..3}, q = 0..15 (module(q) = q>>1).
    float4 w0[16], w1[16];
    #pragma unroll
    for (int q = 0; q < 16; q++) {
        w0[q] = *(const float4*)(W_hh + (size_t)r0 * H + q * 128 + l * 4);
        w1[q] = *(const float4*)(W_hh + (size_t)r1 * H + q * 128 + l * 4);
    }

    // Register h cache, epoch 0 everywhere (h = 0).
    float4 hq[16];
    #pragma unroll
    for (int q = 0; q < 16; q++) hq[q] = make_float4(0.f, 0.f, 0.f, 0.f);

    // Output rows for steps 1 .. period-1 are zero (module inactive, h=0).
    for (int st_ = 1 + l; st_ < period; st_ += 32)
        *(float2*)(out + (size_t)(st_ - 1) * H + r0) = make_float2(0.f, 0.f);

    int budget = 1 << 22;                       // warp-uniform hang guard

    for (int t = period; t <= T_STEPS; t += period) {
        const unsigned tm = (unsigned)(t - 1);
        const unsigned tp = (unsigned)(t - period);
        const unsigned prevm1 = tp ? tp - 1u : 0u;   // epoch view at last activation

        // U for this step (issued first, consumed last).
        const float2 uu = *(const float2*)(g_U + (size_t)tm * H + r0);

        // ---- refresh modules whose epoch advanced; oldest first, module 0 last ----
        #pragma unroll
        for (int i = NMOD - 1; i >= 0; i--) {
            const unsigned e = tm >> i;
            if (e != (prevm1 >> i)) {
                const unsigned expect = 16u * e;
                const unsigned* cp = &g_cnt[i * 32];
                unsigned cv = ld_acq_u32(cp);
                while (cv < expect) {
                    if (--budget < 0) break;    // warp-uniform bail-out
                    cv = ld_acq_u32(cp);
                }
                // epoch e of module i = first burst row of its activation e<<i
                const float* src = out + ((size_t)(e << i) - 1) * H + i * MOD;
                hq[2 * i]     = *(const float4*)(src + 4 * l);
                hq[2 * i + 1] = *(const float4*)(src + 128 + 4 * l);
            }
        }

        // ---- 2x2048 dot: 8 independent FMA chains ----
        float a0x = 0.f, a0y = 0.f, a0z = 0.f, a0w = 0.f;
        float a1x = 0.f, a1y = 0.f, a1z = 0.f, a1w = 0.f;
        #pragma unroll
        for (int q = 0; q < 16; q++) {
            const float4 hv = hq[q];
            a0x = fmaf(hv.x, w0[q].x, a0x);  a0y = fmaf(hv.y, w0[q].y, a0y);
            a0z = fmaf(hv.z, w0[q].z, a0z);  a0w = fmaf(hv.w, w0[q].w, a0w);
            a1x = fmaf(hv.x, w1[q].x, a1x);  a1y = fmaf(hv.y, w1[q].y, a1y);
            a1z = fmaf(hv.z, w1[q].z, a1z);  a1w = fmaf(hv.w, w1[q].w, a1w);
        }
        float a0 = (a0x + a0y) + (a0z + a0w);
        float a1 = (a1x + a1y) + (a1z + a1w);
        #pragma unroll
        for (int off = 16; off >= 1; off >>= 1) {
            a0 += __shfl_xor_sync(0xffffffffu, a0, off);
            a1 += __shfl_xor_sync(0xffffffffu, a1, off);
        }
        const float hc0 = tanhf(uu.x + a0);
        const float hc1 = tanhf(uu.y + a1);

        // ---- publish: first burst row via relaxed store, then CTA release ----
        const unsigned long long packed =
            (unsigned long long)__float_as_uint(hc0) |
            ((unsigned long long)__float_as_uint(hc1) << 32);
        if (l == 0)
            st_rlx_u64((unsigned long long*)(out + (size_t)tm * H + r0), packed);
        __syncthreads();                        // CTA-scope release of all warps' stores
        if (tid == 0) red_rel_add(&g_cnt[j * 32], 1u);

        // ---- remaining carried-output rows of the burst (steps t+1 .. t+period-1) ----
        const int kmax = min(period, T_STEPS - t + 1);
        for (int k = 1 + l; k < kmax; k += 32)
            *(float2*)(out + (size_t)(tm + k) * H + r0) = make_float2(hc0, hc1);
    }
}

// ---------------------------------------------------------------------------
extern "C" void kernel_launch(void* const* d_in, const int* in_sizes, int n_in,
                              void* d_out, int out_size)
{
    const float* x    = (const float*)d_in[0];
    const float* W_ih = (const float*)d_in[1];
    const float* W_hh = (const float*)d_in[2];
    const float* b_ih = (const float*)d_in[3];
    const float* b_hh = (const float*)d_in[4];
    float* out = (float*)d_out;

    input_gemm_kernel<<<dim3(512, NMOD), 256>>>(x, W_ih, b_ih, b_hh);
    recurrence_kernel<<<NGRID, 256>>>(W_hh, out);
}

// round 15
// speedup vs baseline: 4.1850x; 1.4645x over previous
#include <cuda_runtime.h>
#include <cstdint>

#define T_STEPS 4096
#define IN_SZ   1024
#define H       2048
#define MOD     256
#define NMOD    8
#define NWORK   128    // worker CTAs (16 per module); grid padded to 148
#define NGRID   148
#define RING    8      // tagged-value ring slots per module (>=3 structurally safe)

// ---------------------------------------------------------------------------
// Scratch (static device memory; no allocations allowed)
// ---------------------------------------------------------------------------
__device__ float g_U[(size_t)T_STEPS * H];   // 32MB: U[t-1][r] = x·W_ih^T + b_ih + b_hh

// Tagged-value ring: word = (epoch << 32) | f32_bits.
// g_tv[(module*RING + (epoch & 7))*256 + col]. Zero-init == epoch 0, h = 0.
#define GTV_WORDS (NMOD * RING * 256)        // 16384 u64 = 128KB
__device__ __align__(16) unsigned long long g_tv[GTV_WORDS];

// ---------------------------------------------------------------------------
// relaxed 64-bit primitives (single-word atomicity carries tag+value together)
// ---------------------------------------------------------------------------
__device__ __forceinline__ unsigned long long ld_rlx(const unsigned long long* p) {
    unsigned long long v;
    asm volatile("ld.relaxed.gpu.global.b64 %0, [%1];" : "=l"(v) : "l"(p));
    return v;
}
__device__ __forceinline__ void st_rlx(unsigned long long* p, unsigned long long v) {
    asm volatile("st.relaxed.gpu.global.b64 [%0], %1;" :: "l"(p), "l"(v));
}
__device__ __forceinline__ float lof(unsigned long long v) {
    return __uint_as_float((unsigned)v);
}

// ---------------------------------------------------------------------------
// Kernel 1: zero the tagged ring + input projection for active (step, module)
// pairs. grid = (512, 8); CTA (bx, j) handles 8 active steps of module j.
// Blocks with blk = j*512+bx < 32 zero g_tv (32*256 float4 = 128KB exactly).
// ---------------------------------------------------------------------------
__global__ __launch_bounds__(256) void input_gemm_kernel(
    const float* __restrict__ x, const float* __restrict__ W_ih,
    const float* __restrict__ b_ih, const float* __restrict__ b_hh)
{
    const int j   = blockIdx.y;
    const int bx  = blockIdx.x;
    const int tid = threadIdx.x;

    {   // zero the ring (16384 u64 = 8192 float4)
        const int blk = j * 512 + bx;
        if (blk < 32)
            ((float4*)g_tv)[blk * 256 + tid] = make_float4(0.f, 0.f, 0.f, 0.f);
    }

    const int nb = (T_STEPS >> j) >> 3;
    if (bx >= nb) return;
    const int p = 1 << j;

    __shared__ float4 xs[8][IN_SZ / 4];                     // 32 KB
    #pragma unroll
    for (int k = 0; k < 8; k++) {
        int t = p * (bx * 8 + k + 1);                       // 1-indexed active step
        const float4* xr = (const float4*)(x + (size_t)(t - 1) * IN_SZ);
        xs[k][tid] = xr[tid];
    }
    __syncthreads();

    const int r = j * MOD + tid;
    const float4* wr = (const float4*)(W_ih + (size_t)r * IN_SZ);
    float acc[8] = {0.f, 0.f, 0.f, 0.f, 0.f, 0.f, 0.f, 0.f};
    #pragma unroll 2
    for (int q = 0; q < IN_SZ / 4; q++) {
        const float4 w = wr[q];
        #pragma unroll
        for (int k = 0; k < 8; k++) {
            const float4 xv = xs[k][q];
            acc[k] = fmaf(w.x, xv.x, fmaf(w.y, xv.y, fmaf(w.z, xv.z, fmaf(w.w, xv.w, acc[k]))));
        }
    }
    const float b = b_ih[r] + b_hh[r];
    #pragma unroll
    for (int k = 0; k < 8; k++) {
        int t = p * (bx * 8 + k + 1);
        g_U[(size_t)(t - 1) * H + r] = acc[k] + b;
    }
}

// ---------------------------------------------------------------------------
// Kernel 2: module-partitioned recurrence with tagged-value ring + cached
// per-module partial sums. Worker CTA g (<128): module j = g>>4, sub s = g&15;
// warp w owns rows r0 = j*256 + s*16 + 2w, r1 = r0+1; iterates only
// t = 2^j, 2*2^j, ... Per iteration:
//   - thread tid spins on ONE tagged word per refreshed module (tag==epoch),
//     stages value into parity smem buffer; one __syncthreads;
//   - warps recompute ONLY refreshed modules' partial dots (16 FMA each),
//     sum 8 cached partials, butterfly, tanh;
//   - lane0 publishes two tagged words (one hop: readiness == data);
//   - all lanes stripe the output burst.
// Overwrite safety of the 8-slot ring is structural: every CTA reads every
// module at refresh, so any owner's frontier is gated <= 1 epoch past any
// laggard's need (mutual gating), far inside the 7-epoch ring margin.
// ---------------------------------------------------------------------------
__global__ __launch_bounds__(256, 1) void recurrence_kernel(
    const float* __restrict__ W_hh, float* __restrict__ out)
{
    const int g = blockIdx.x;
    if (g >= NWORK) return;                     // grid padded to 148
    const int j = g >> 4;                       // owned module
    const int s = g & 15;                       // sub-index within module
    const int tid = threadIdx.x;
    const int w   = tid >> 5;
    const int l   = tid & 31;
    const int r0  = j * MOD + s * 16 + 2 * w;
    const int r1  = r0 + 1;
    const int period = 1 << j;

    __shared__ __align__(16) float hsm[2][H];   // parity-buffered staged h (16KB)

    // This warp's two W_hh rows -> registers (128 f32/lane):
    // lane l covers columns 128q + 4l + {0..3}; module(q) = q>>1.
    float4 w0[16], w1[16];
    #pragma unroll
    for (int q = 0; q < 16; q++) {
        w0[q] = *(const float4*)(W_hh + (size_t)r0 * H + q * 128 + l * 4);
        w1[q] = *(const float4*)(W_hh + (size_t)r1 * H + q * 128 + l * 4);
    }

    // Cached per-module partial dots (epoch-0 h = 0 -> partials 0).
    float pa0[NMOD], pa1[NMOD];
    #pragma unroll
    for (int i = 0; i < NMOD; i++) { pa0[i] = 0.f; pa1[i] = 0.f; }

    // Output rows for steps 1 .. period-1 are zero (module inactive, h=0).
    for (int k = 1 + l; k < period; k += 32)
        *(float2*)(out + (size_t)(k - 1) * H + r0) = make_float2(0.f, 0.f);

    int budget = 1 << 22;                       // hang guard
    int par = 0;

    for (int t = period; t <= T_STEPS; t += period, par ^= 1) {
        const unsigned tm  = (unsigned)(t - 1);
        const unsigned ptm = (t == period) ? 0u : (unsigned)(t - period - 1);

        // U for this step (issued early, consumed last).
        const float2 uu = *(const float2*)(g_U + (size_t)tm * H + r0);

        // ---- stage refreshed modules: one tagged word per thread ----
        float* buf = hsm[par];
        unsigned refreshed = 0u;
        #pragma unroll
        for (int i = NMOD - 1; i >= 0; i--) {
            const unsigned e = tm >> i;
            if (e != (ptm >> i)) {
                refreshed |= (1u << i);
                const unsigned long long* p =
                    &g_tv[((size_t)i * RING + (e & (RING - 1))) * 256 + tid];
                unsigned long long v = ld_rlx(p);
                while ((unsigned)(v >> 32) != e) {
                    if (--budget < 0) break;    // hang guard
                    v = ld_rlx(p);
                }
                buf[i * 256 + tid] = lof(v);
            }
        }
        __syncthreads();

        // ---- recompute partial dots for refreshed modules only ----
        #pragma unroll
        for (int i = 0; i < NMOD; i++) {
            if (refreshed & (1u << i)) {
                const float4 h0 = *(const float4*)(buf + i * 256 + 4 * l);
                const float4 h1 = *(const float4*)(buf + i * 256 + 128 + 4 * l);
                const float4 wa = w0[2 * i], wb = w0[2 * i + 1];
                const float4 wc = w1[2 * i], wd = w1[2 * i + 1];
                float u0 = fmaf(h0.x, wa.x, fmaf(h0.y, wa.y, fmaf(h0.z, wa.z, h0.w * wa.w)));
                float v0 = fmaf(h1.x, wb.x, fmaf(h1.y, wb.y, fmaf(h1.z, wb.z, h1.w * wb.w)));
                float u1 = fmaf(h0.x, wc.x, fmaf(h0.y, wc.y, fmaf(h0.z, wc.z, h0.w * wc.w)));
                float v1 = fmaf(h1.x, wd.x, fmaf(h1.y, wd.y, fmaf(h1.z, wd.z, h1.w * wd.w)));
                pa0[i] = u0 + v0;
                pa1[i] = u1 + v1;
            }
        }

        // ---- total pre-activation: sum cached partials + butterfly ----
        float a0 = ((pa0[0] + pa0[1]) + (pa0[2] + pa0[3])) +
                   ((pa0[4] + pa0[5]) + (pa0[6] + pa0[7]));
        float a1 = ((pa1[0] + pa1[1]) + (pa1[2] + pa1[3])) +
                   ((pa1[4] + pa1[5]) + (pa1[6] + pa1[7]));
        #pragma unroll
        for (int off = 16; off >= 1; off >>= 1) {
            a0 += __shfl_xor_sync(0xffffffffu, a0, off);
            a1 += __shfl_xor_sync(0xffffffffu, a1, off);
        }
        const float hc0 = tanhf(uu.x + a0);
        const float hc1 = tanhf(uu.y + a1);

        // ---- publish: one hop — tagged words carry readiness AND data ----
        if (l == 0) {
            const unsigned e = (unsigned)t >> j;
            unsigned long long* p =
                &g_tv[((size_t)j * RING + (e & (RING - 1))) * 256 + (s * 16 + 2 * w)];
            const unsigned long long hi = (unsigned long long)e << 32;
            st_rlx(p,     hi | (unsigned long long)__float_as_uint(hc0));
            st_rlx(p + 1, hi | (unsigned long long)__float_as_uint(hc1));
        }

        // ---- output burst: value holds for steps t .. t+period-1 ----
        const int kmax = min(period, T_STEPS - t + 1);
        for (int k = l; k < kmax; k += 32)
            *(float2*)(out + (size_t)(tm + k) * H + r0) = make_float2(hc0, hc1);
    }
}

// ---------------------------------------------------------------------------
extern "C" void kernel_launch(void* const* d_in, const int* in_sizes, int n_in,
                              void* d_out, int out_size)
{
    const float* x    = (const float*)d_in[0];
    const float* W_ih = (const float*)d_in[1];
    const float* W_hh = (const float*)d_in[2];
    const float* b_ih = (const float*)d_in[3];
    const float* b_hh = (const float*)d_in[4];
    float* out = (float*)d_out;

    input_gemm_kernel<<<dim3(512, NMOD), 256>>>(x, W_ih, b_ih, b_hh);
    recurrence_kernel<<<NGRID, 256>>>(W_hh, out);
}